// round 1
// baseline (speedup 1.0000x reference)
#include <cuda_runtime.h>
#include <cuda_bf16.h>

#define OUT_F 4096
#define IN_F  2048
#define KDIM  4096   // 2*IN_F logical K
#define BATCH 4096

// Dense decompressed weight scratch (64 MB) — __device__ global, no allocation.
__device__ float g_Wd[(size_t)OUT_F * KDIM];

// ---------------------------------------------------------------------------
// Kernel 1: decompress (weight, metadata) -> dense logical-K weight g_Wd.
// One thread per group of 4 logical columns (2 compressed elements).
// ---------------------------------------------------------------------------
__global__ void decompress_kernel(const float* __restrict__ w,
                                  const int* __restrict__ meta) {
    int idx = blockIdx.x * blockDim.x + threadIdx.x;   // r * 1024 + g
    int r = idx >> 10;
    int g = idx & 1023;
    const float2 wv = *reinterpret_cast<const float2*>(w    + (size_t)r * IN_F + 2 * g);
    const int2   mv = *reinterpret_cast<const int2*>  (meta + (size_t)r * IN_F + 2 * g);
    // mv.x, mv.y in 0..3, distinct (sorted pair from LUT)
    float4 v;
    v.x = (mv.x == 0) ? wv.x : ((mv.y == 0) ? wv.y : 0.f);
    v.y = (mv.x == 1) ? wv.x : ((mv.y == 1) ? wv.y : 0.f);
    v.z = (mv.x == 2) ? wv.x : ((mv.y == 2) ? wv.y : 0.f);
    v.w = (mv.x == 3) ? wv.x : ((mv.y == 3) ? wv.y : 0.f);
    *reinterpret_cast<float4*>(g_Wd + (size_t)r * KDIM + 4 * g) = v;
}

// ---------------------------------------------------------------------------
// Kernel 2: SGEMM D = Wd @ input^T over compressed rows, scatter epilogue.
// Block tile 128x128, K-tile 8, 256 threads, 8x8 micro-tile per thread.
// Smem rows padded to 132 floats: conflict-free transposed STS, aligned LDS.128.
// ---------------------------------------------------------------------------
#define BM 128
#define BN 128
#define BK 8
#define LDA 132   // padded row length (floats); 132*4 = 528 B (16B-aligned)

__global__ __launch_bounds__(256, 2) void sgemm_scatter_kernel(
    const float* __restrict__ Bmat,     // input [BATCH][KDIM], K-contiguous
    const int*   __restrict__ indices,  // [OUT_F] logical row ids
    float*       __restrict__ out)      // [2*OUT_F][BATCH]
{
    __shared__ float As[BK][LDA];
    __shared__ float Bs[BK][LDA];

    const int tid = threadIdx.x;
    const int tx  = tid & 15;   // 16 cols of threads -> N
    const int ty  = tid >> 4;   // 16 rows of threads -> M

    const float* Aptr = g_Wd + (size_t)blockIdx.y * BM * KDIM;
    const float* Bptr = Bmat + (size_t)blockIdx.x * BN * KDIM;

    const int ld_row = tid >> 1;          // 0..127
    const int ld_col = (tid & 1) * 4;     // 0 or 4

    float acc[8][8] = {};

    // prefetch first K-tile into registers
    float4 a = *reinterpret_cast<const float4*>(Aptr + (size_t)ld_row * KDIM + ld_col);
    float4 b = *reinterpret_cast<const float4*>(Bptr + (size_t)ld_row * KDIM + ld_col);

    for (int k0 = 0; k0 < KDIM; k0 += BK) {
        As[ld_col + 0][ld_row] = a.x; As[ld_col + 1][ld_row] = a.y;
        As[ld_col + 2][ld_row] = a.z; As[ld_col + 3][ld_row] = a.w;
        Bs[ld_col + 0][ld_row] = b.x; Bs[ld_col + 1][ld_row] = b.y;
        Bs[ld_col + 2][ld_row] = b.z; Bs[ld_col + 3][ld_row] = b.w;
        __syncthreads();

        if (k0 + BK < KDIM) {   // prefetch next K-tile (hides GMEM latency)
            a = *reinterpret_cast<const float4*>(Aptr + (size_t)ld_row * KDIM + (k0 + BK) + ld_col);
            b = *reinterpret_cast<const float4*>(Bptr + (size_t)ld_row * KDIM + (k0 + BK) + ld_col);
        }

        #pragma unroll
        for (int kk = 0; kk < BK; kk++) {
            float4 a0 = *reinterpret_cast<const float4*>(&As[kk][ty * 8]);
            float4 a1 = *reinterpret_cast<const float4*>(&As[kk][ty * 8 + 4]);
            float4 b0 = *reinterpret_cast<const float4*>(&Bs[kk][tx * 8]);
            float4 b1 = *reinterpret_cast<const float4*>(&Bs[kk][tx * 8 + 4]);
            float ar[8] = {a0.x, a0.y, a0.z, a0.w, a1.x, a1.y, a1.z, a1.w};
            float br[8] = {b0.x, b0.y, b0.z, b0.w, b1.x, b1.y, b1.z, b1.w};
            #pragma unroll
            for (int i = 0; i < 8; i++)
                #pragma unroll
                for (int j = 0; j < 8; j++)
                    acc[i][j] += ar[i] * br[j];
        }
        __syncthreads();
    }

    // Epilogue: scatter computed rows; zero sibling rows (covers full output).
    const int n0 = blockIdx.x * BN + tx * 8;
    const float4 z4 = make_float4(0.f, 0.f, 0.f, 0.f);
    #pragma unroll
    for (int i = 0; i < 8; i++) {
        int r   = blockIdx.y * BM + ty * 8 + i;
        int idx = indices[r];
        float* orow = out + (size_t)idx * BATCH + n0;
        float* zrow = out + (size_t)(idx ^ 1) * BATCH + n0;
        *reinterpret_cast<float4*>(orow)     = make_float4(acc[i][0], acc[i][1], acc[i][2], acc[i][3]);
        *reinterpret_cast<float4*>(orow + 4) = make_float4(acc[i][4], acc[i][5], acc[i][6], acc[i][7]);
        *reinterpret_cast<float4*>(zrow)     = z4;
        *reinterpret_cast<float4*>(zrow + 4) = z4;
    }
}

// ---------------------------------------------------------------------------
extern "C" void kernel_launch(void* const* d_in, const int* in_sizes, int n_in,
                              void* d_out, int out_size) {
    const float* weight   = (const float*)d_in[0];
    const int*   indices  = (const int*)  d_in[1];
    const int*   metadata = (const int*)  d_in[2];
    const float* input    = (const float*)d_in[3];
    float*       out      = (float*)d_out;

    // 1 thread per 4 logical cols: OUT_F * IN_F/2 threads
    decompress_kernel<<<(OUT_F * (IN_F / 2)) / 256, 256>>>(weight, metadata);

    dim3 grid(BATCH / BN, OUT_F / BM);
    sgemm_scatter_kernel<<<grid, 256>>>(input, indices, out);
}

// round 2
// speedup vs baseline: 1.0003x; 1.0003x over previous
#include <cuda_runtime.h>
#include <cuda_bf16.h>

#define OUT_F 4096
#define IN_F  2048
#define KDIM  4096   // 2*IN_F logical K
#define BATCH 4096

// Dense decompressed weight scratch (64 MB) — __device__ global, no allocation.
__device__ float g_Wd[(size_t)OUT_F * KDIM];

// ---------------------------------------------------------------------------
// Kernel 1: decompress (weight, metadata) -> dense logical-K weight g_Wd.
// One thread per group of 4 logical columns (2 compressed elements).
// ---------------------------------------------------------------------------
__global__ void decompress_kernel(const float* __restrict__ w,
                                  const int* __restrict__ meta) {
    int idx = blockIdx.x * blockDim.x + threadIdx.x;   // r * 1024 + g
    int r = idx >> 10;
    int g = idx & 1023;
    const float2 wv = *reinterpret_cast<const float2*>(w    + (size_t)r * IN_F + 2 * g);
    const int2   mv = *reinterpret_cast<const int2*>  (meta + (size_t)r * IN_F + 2 * g);
    // mv.x, mv.y in 0..3, distinct (sorted pair from LUT)
    float4 v;
    v.x = (mv.x == 0) ? wv.x : ((mv.y == 0) ? wv.y : 0.f);
    v.y = (mv.x == 1) ? wv.x : ((mv.y == 1) ? wv.y : 0.f);
    v.z = (mv.x == 2) ? wv.x : ((mv.y == 2) ? wv.y : 0.f);
    v.w = (mv.x == 3) ? wv.x : ((mv.y == 3) ? wv.y : 0.f);
    *reinterpret_cast<float4*>(g_Wd + (size_t)r * KDIM + 4 * g) = v;
}

// ---------------------------------------------------------------------------
// Kernel 2: SGEMM D = Wd @ input^T over compressed rows, scatter epilogue.
// Block tile 128x128, K-tile 8, 256 threads, 8x8 micro-tile per thread.
// Smem rows padded to 132 floats: conflict-free transposed STS, aligned LDS.128.
// ---------------------------------------------------------------------------
#define BM 128
#define BN 128
#define BK 8
#define LDA 132   // padded row length (floats); 132*4 = 528 B (16B-aligned)

__global__ __launch_bounds__(256, 2) void sgemm_scatter_kernel(
    const float* __restrict__ Bmat,     // input [BATCH][KDIM], K-contiguous
    const int*   __restrict__ indices,  // [OUT_F] logical row ids
    float*       __restrict__ out)      // [2*OUT_F][BATCH]
{
    __shared__ float As[BK][LDA];
    __shared__ float Bs[BK][LDA];

    const int tid = threadIdx.x;
    const int tx  = tid & 15;   // 16 cols of threads -> N
    const int ty  = tid >> 4;   // 16 rows of threads -> M

    const float* Aptr = g_Wd + (size_t)blockIdx.y * BM * KDIM;
    const float* Bptr = Bmat + (size_t)blockIdx.x * BN * KDIM;

    const int ld_row = tid >> 1;          // 0..127
    const int ld_col = (tid & 1) * 4;     // 0 or 4

    float acc[8][8] = {};

    // prefetch first K-tile into registers
    float4 a = *reinterpret_cast<const float4*>(Aptr + (size_t)ld_row * KDIM + ld_col);
    float4 b = *reinterpret_cast<const float4*>(Bptr + (size_t)ld_row * KDIM + ld_col);

    for (int k0 = 0; k0 < KDIM; k0 += BK) {
        As[ld_col + 0][ld_row] = a.x; As[ld_col + 1][ld_row] = a.y;
        As[ld_col + 2][ld_row] = a.z; As[ld_col + 3][ld_row] = a.w;
        Bs[ld_col + 0][ld_row] = b.x; Bs[ld_col + 1][ld_row] = b.y;
        Bs[ld_col + 2][ld_row] = b.z; Bs[ld_col + 3][ld_row] = b.w;
        __syncthreads();

        if (k0 + BK < KDIM) {   // prefetch next K-tile (hides GMEM latency)
            a = *reinterpret_cast<const float4*>(Aptr + (size_t)ld_row * KDIM + (k0 + BK) + ld_col);
            b = *reinterpret_cast<const float4*>(Bptr + (size_t)ld_row * KDIM + (k0 + BK) + ld_col);
        }

        #pragma unroll
        for (int kk = 0; kk < BK; kk++) {
            float4 a0 = *reinterpret_cast<const float4*>(&As[kk][ty * 8]);
            float4 a1 = *reinterpret_cast<const float4*>(&As[kk][ty * 8 + 4]);
            float4 b0 = *reinterpret_cast<const float4*>(&Bs[kk][tx * 8]);
            float4 b1 = *reinterpret_cast<const float4*>(&Bs[kk][tx * 8 + 4]);
            float ar[8] = {a0.x, a0.y, a0.z, a0.w, a1.x, a1.y, a1.z, a1.w};
            float br[8] = {b0.x, b0.y, b0.z, b0.w, b1.x, b1.y, b1.z, b1.w};
            #pragma unroll
            for (int i = 0; i < 8; i++)
                #pragma unroll
                for (int j = 0; j < 8; j++)
                    acc[i][j] += ar[i] * br[j];
        }
        __syncthreads();
    }

    // Epilogue: scatter computed rows; zero sibling rows (covers full output).
    const int n0 = blockIdx.x * BN + tx * 8;
    const float4 z4 = make_float4(0.f, 0.f, 0.f, 0.f);
    #pragma unroll
    for (int i = 0; i < 8; i++) {
        int r   = blockIdx.y * BM + ty * 8 + i;
        int idx = indices[r];
        float* orow = out + (size_t)idx * BATCH + n0;
        float* zrow = out + (size_t)(idx ^ 1) * BATCH + n0;
        *reinterpret_cast<float4*>(orow)     = make_float4(acc[i][0], acc[i][1], acc[i][2], acc[i][3]);
        *reinterpret_cast<float4*>(orow + 4) = make_float4(acc[i][4], acc[i][5], acc[i][6], acc[i][7]);
        *reinterpret_cast<float4*>(zrow)     = z4;
        *reinterpret_cast<float4*>(zrow + 4) = z4;
    }
}

// ---------------------------------------------------------------------------
extern "C" void kernel_launch(void* const* d_in, const int* in_sizes, int n_in,
                              void* d_out, int out_size) {
    const float* weight   = (const float*)d_in[0];
    const int*   indices  = (const int*)  d_in[1];
    const int*   metadata = (const int*)  d_in[2];
    const float* input    = (const float*)d_in[3];
    float*       out      = (float*)d_out;

    // 1 thread per 4 logical cols: OUT_F * IN_F/2 threads
    decompress_kernel<<<(OUT_F * (IN_F / 2)) / 256, 256>>>(weight, metadata);

    dim3 grid(BATCH / BN, OUT_F / BM);
    sgemm_scatter_kernel<<<grid, 256>>>(input, indices, out);
}

// round 3
// speedup vs baseline: 1.0011x; 1.0008x over previous
#include <cuda_runtime.h>
#include <cuda_bf16.h>

#define OUT_F 4096
#define IN_F  2048
#define KDIM  4096   // 2*IN_F logical K
#define BATCH 4096

// Dense decompressed weight scratch (64 MB) — __device__ global, no allocation.
__device__ float g_Wd[(size_t)OUT_F * KDIM];

// ---------------------------------------------------------------------------
// Kernel 1: decompress (weight, metadata) -> dense logical-K weight g_Wd.
// One thread per group of 4 logical columns (2 compressed elements).
// ---------------------------------------------------------------------------
__global__ void decompress_kernel(const float* __restrict__ w,
                                  const int* __restrict__ meta) {
    int idx = blockIdx.x * blockDim.x + threadIdx.x;   // r * 1024 + g
    int r = idx >> 10;
    int g = idx & 1023;
    const float2 wv = *reinterpret_cast<const float2*>(w    + (size_t)r * IN_F + 2 * g);
    const int2   mv = *reinterpret_cast<const int2*>  (meta + (size_t)r * IN_F + 2 * g);
    // mv.x, mv.y in 0..3, distinct (sorted pair from LUT)
    float4 v;
    v.x = (mv.x == 0) ? wv.x : ((mv.y == 0) ? wv.y : 0.f);
    v.y = (mv.x == 1) ? wv.x : ((mv.y == 1) ? wv.y : 0.f);
    v.z = (mv.x == 2) ? wv.x : ((mv.y == 2) ? wv.y : 0.f);
    v.w = (mv.x == 3) ? wv.x : ((mv.y == 3) ? wv.y : 0.f);
    *reinterpret_cast<float4*>(g_Wd + (size_t)r * KDIM + 4 * g) = v;
}

// ---------------------------------------------------------------------------
// Kernel 2: SGEMM D = Wd @ input^T over compressed rows, scatter epilogue.
// Block tile 128x128, K-tile 8, 256 threads, 8x8 micro-tile per thread.
// Smem rows padded to 132 floats: conflict-free transposed STS, aligned LDS.128.
// ---------------------------------------------------------------------------
#define BM 128
#define BN 128
#define BK 8
#define LDA 132   // padded row length (floats); 132*4 = 528 B (16B-aligned)

__global__ __launch_bounds__(256, 2) void sgemm_scatter_kernel(
    const float* __restrict__ Bmat,     // input [BATCH][KDIM], K-contiguous
    const int*   __restrict__ indices,  // [OUT_F] logical row ids
    float*       __restrict__ out)      // [2*OUT_F][BATCH]
{
    __shared__ float As[BK][LDA];
    __shared__ float Bs[BK][LDA];

    const int tid = threadIdx.x;
    const int tx  = tid & 15;   // 16 cols of threads -> N
    const int ty  = tid >> 4;   // 16 rows of threads -> M

    const float* Aptr = g_Wd + (size_t)blockIdx.y * BM * KDIM;
    const float* Bptr = Bmat + (size_t)blockIdx.x * BN * KDIM;

    const int ld_row = tid >> 1;          // 0..127
    const int ld_col = (tid & 1) * 4;     // 0 or 4

    float acc[8][8] = {};

    // prefetch first K-tile into registers
    float4 a = *reinterpret_cast<const float4*>(Aptr + (size_t)ld_row * KDIM + ld_col);
    float4 b = *reinterpret_cast<const float4*>(Bptr + (size_t)ld_row * KDIM + ld_col);

    for (int k0 = 0; k0 < KDIM; k0 += BK) {
        As[ld_col + 0][ld_row] = a.x; As[ld_col + 1][ld_row] = a.y;
        As[ld_col + 2][ld_row] = a.z; As[ld_col + 3][ld_row] = a.w;
        Bs[ld_col + 0][ld_row] = b.x; Bs[ld_col + 1][ld_row] = b.y;
        Bs[ld_col + 2][ld_row] = b.z; Bs[ld_col + 3][ld_row] = b.w;
        __syncthreads();

        if (k0 + BK < KDIM) {   // prefetch next K-tile (hides GMEM latency)
            a = *reinterpret_cast<const float4*>(Aptr + (size_t)ld_row * KDIM + (k0 + BK) + ld_col);
            b = *reinterpret_cast<const float4*>(Bptr + (size_t)ld_row * KDIM + (k0 + BK) + ld_col);
        }

        #pragma unroll
        for (int kk = 0; kk < BK; kk++) {
            float4 a0 = *reinterpret_cast<const float4*>(&As[kk][ty * 8]);
            float4 a1 = *reinterpret_cast<const float4*>(&As[kk][ty * 8 + 4]);
            float4 b0 = *reinterpret_cast<const float4*>(&Bs[kk][tx * 8]);
            float4 b1 = *reinterpret_cast<const float4*>(&Bs[kk][tx * 8 + 4]);
            float ar[8] = {a0.x, a0.y, a0.z, a0.w, a1.x, a1.y, a1.z, a1.w};
            float br[8] = {b0.x, b0.y, b0.z, b0.w, b1.x, b1.y, b1.z, b1.w};
            #pragma unroll
            for (int i = 0; i < 8; i++)
                #pragma unroll
                for (int j = 0; j < 8; j++)
                    acc[i][j] += ar[i] * br[j];
        }
        __syncthreads();
    }

    // Epilogue: scatter computed rows; zero sibling rows (covers full output).
    const int n0 = blockIdx.x * BN + tx * 8;
    const float4 z4 = make_float4(0.f, 0.f, 0.f, 0.f);
    #pragma unroll
    for (int i = 0; i < 8; i++) {
        int r   = blockIdx.y * BM + ty * 8 + i;
        int idx = indices[r];
        float* orow = out + (size_t)idx * BATCH + n0;
        float* zrow = out + (size_t)(idx ^ 1) * BATCH + n0;
        *reinterpret_cast<float4*>(orow)     = make_float4(acc[i][0], acc[i][1], acc[i][2], acc[i][3]);
        *reinterpret_cast<float4*>(orow + 4) = make_float4(acc[i][4], acc[i][5], acc[i][6], acc[i][7]);
        *reinterpret_cast<float4*>(zrow)     = z4;
        *reinterpret_cast<float4*>(zrow + 4) = z4;
    }
}

// ---------------------------------------------------------------------------
extern "C" void kernel_launch(void* const* d_in, const int* in_sizes, int n_in,
                              void* d_out, int out_size) {
    const float* weight   = (const float*)d_in[0];
    const int*   indices  = (const int*)  d_in[1];
    const int*   metadata = (const int*)  d_in[2];
    const float* input    = (const float*)d_in[3];
    float*       out      = (float*)d_out;

    // 1 thread per 4 logical cols: OUT_F * IN_F/2 threads
    decompress_kernel<<<(OUT_F * (IN_F / 2)) / 256, 256>>>(weight, metadata);

    dim3 grid(BATCH / BN, OUT_F / BM);
    sgemm_scatter_kernel<<<grid, 256>>>(input, indices, out);
}